// round 5
// baseline (speedup 1.0000x reference)
#include <cuda_runtime.h>
#include <math.h>
#include <mma.h>

using namespace nvcuda;

#define N_NODES 100000
#define E_EDGES 400000
#define IN_DIM  100
#define D       200
#define D3      600
#define NUM_STEPS 4

// ---------------- scratch (static device globals; 16B-aligned) ---------------
__device__ __align__(16) float g_h   [(size_t)N_NODES * D];
__device__ __align__(16) float g_h2  [(size_t)N_NODES * D];
__device__ __align__(16) float g_m   [(size_t)N_NODES * D];
__device__ __align__(16) float g_aggr[(size_t)N_NODES * D];
__device__ __align__(16) float g_Bih [D * D3];
__device__ __align__(16) float g_Bhh [D * D3];
__device__ __align__(16) float g_pool[D];
__device__ int g_src[E_EDGES];
__device__ int g_dst[E_EDGES];
__device__ int g_ei_is64;

// ---------------- edge-index dtype detection + conversion --------------------
__global__ void detect_ei_kernel(const unsigned int* __restrict__ w) {
    if (threadIdx.x == 0) {
        int is64 = 1;
        for (int i = 0; i < 4096; i++)
            if (w[2 * i + 1] != 0u) { is64 = 0; break; }
        g_ei_is64 = is64;
    }
}

__global__ void convert_ei_kernel(const void* __restrict__ ei) {
    int e = blockIdx.x * blockDim.x + threadIdx.x;
    if (e >= E_EDGES) return;
    int s, d;
    if (g_ei_is64) {
        const long long* p = (const long long*)ei;
        s = (int)p[e];
        d = (int)p[E_EDGES + e];
    } else {
        const int* p = (const int*)ei;
        s = p[e];
        d = p[E_EDGES + e];
    }
    s = min(max(s, 0), N_NODES - 1);
    d = min(max(d, 0), N_NODES - 1);
    g_src[e] = s;
    g_dst[e] = d;
}

// ---------------- helpers ----------------------------------------------------
__global__ void zero4_kernel(float* __restrict__ p, int n4) {
    int i = blockIdx.x * blockDim.x + threadIdx.x;
    if (i < n4) ((float4*)p)[i] = make_float4(0.f, 0.f, 0.f, 0.f);
}

__global__ void init_h_kernel(const float* __restrict__ x) {
    int idx = blockIdx.x * blockDim.x + threadIdx.x;
    if (idx >= N_NODES * D) return;
    int n = idx / D, d = idx - n * D;
    g_h[idx] = (d < IN_DIM) ? x[n * IN_DIM + d] : 0.f;
}

// w: [D3, D] row-major  ->  o: [D, D3] row-major  (o = w^T)
__global__ void transpose_kernel(const float* __restrict__ w, float* __restrict__ o) {
    int idx = blockIdx.x * blockDim.x + threadIdx.x;
    if (idx >= D3 * D) return;
    int r = idx / D, c = idx - r * D;
    o[c * D3 + r] = w[idx];
}

// ---------------- TF32 tensor-core GEMM: C[M,Nc] = A[M,K] @ B[K,Nc] ----------
// (unchanged from R4; used for m = h @ W[step])
#define BMG 128
#define BNG 128
#define BKG 16
#define GA_LD 20
#define GB_LD 132
#define GC_LD 68
#define GSMEM_A (BMG * GA_LD)
#define GSMEM_B (BKG * GB_LD)
#define GSMEM_C (8 * 32 * GC_LD)
#define GEMM_SMEM_BYTES ((GSMEM_A + GSMEM_B + GSMEM_C) * 4)

__global__ __launch_bounds__(256) void gemm_tf32(
    const float* __restrict__ A, const float* __restrict__ B, float* __restrict__ C,
    int M, int Nc, int K)
{
    extern __shared__ float smem[];
    float* As = smem;
    float* Bs = As + GSMEM_A;
    float* Cs = Bs + GSMEM_B;

    const int tid  = threadIdx.x;
    const int wid  = tid >> 5;
    const int lane = tid & 31;
    const int wm   = wid & 3;
    const int wn   = wid >> 2;
    const int rowBase = blockIdx.y * BMG;
    const int colBase = blockIdx.x * BNG;

    wmma::fragment<wmma::accumulator, 16, 16, 8, float> c[2][4];
#pragma unroll
    for (int i = 0; i < 2; i++)
#pragma unroll
        for (int j = 0; j < 4; j++) wmma::fill_fragment(c[i][j], 0.f);

    for (int k0 = 0; k0 < K; k0 += BKG) {
#pragma unroll
        for (int f = tid; f < 512; f += 256) {
            int r = f >> 2, cc = (f & 3) * 4;
            float4 v = make_float4(0.f, 0.f, 0.f, 0.f);
            int gr = rowBase + r, gc = k0 + cc;
            if (gr < M) {
                const float* src = A + (size_t)gr * K + gc;
                if (gc + 3 < K) v = *(const float4*)src;
                else {
                    if (gc + 0 < K) v.x = src[0];
                    if (gc + 1 < K) v.y = src[1];
                    if (gc + 2 < K) v.z = src[2];
                }
            }
            v.x = wmma::__float_to_tf32(v.x); v.y = wmma::__float_to_tf32(v.y);
            v.z = wmma::__float_to_tf32(v.z); v.w = wmma::__float_to_tf32(v.w);
            *(float4*)(As + r * GA_LD + cc) = v;
        }
#pragma unroll
        for (int f = tid; f < 512; f += 256) {
            int r = f >> 5, cc = (f & 31) * 4;
            float4 v = make_float4(0.f, 0.f, 0.f, 0.f);
            int gr = k0 + r, gc = colBase + cc;
            if (gr < K) {
                const float* src = B + (size_t)gr * Nc + gc;
                if (gc + 3 < Nc) v = *(const float4*)src;
                else {
                    if (gc + 0 < Nc) v.x = src[0];
                    if (gc + 1 < Nc) v.y = src[1];
                    if (gc + 2 < Nc) v.z = src[2];
                }
            }
            v.x = wmma::__float_to_tf32(v.x); v.y = wmma::__float_to_tf32(v.y);
            v.z = wmma::__float_to_tf32(v.z); v.w = wmma::__float_to_tf32(v.w);
            *(float4*)(Bs + r * GB_LD + cc) = v;
        }
        __syncthreads();

#pragma unroll
        for (int ks = 0; ks < 2; ks++) {
            const int kk = ks * 8;
            wmma::fragment<wmma::matrix_a, 16, 16, 8, wmma::precision::tf32, wmma::row_major> a0, a1;
            wmma::load_matrix_sync(a0, As + (wm * 32 + 0)  * GA_LD + kk, GA_LD);
            wmma::load_matrix_sync(a1, As + (wm * 32 + 16) * GA_LD + kk, GA_LD);
#pragma unroll
            for (int j = 0; j < 4; j++) {
                wmma::fragment<wmma::matrix_b, 16, 16, 8, wmma::precision::tf32, wmma::row_major> b;
                wmma::load_matrix_sync(b, Bs + kk * GB_LD + wn * 64 + j * 16, GB_LD);
                wmma::mma_sync(c[0][j], a0, b, c[0][j]);
                wmma::mma_sync(c[1][j], a1, b, c[1][j]);
            }
        }
        __syncthreads();
    }

    float* myCs = Cs + wid * (32 * GC_LD);
#pragma unroll
    for (int i = 0; i < 2; i++)
#pragma unroll
        for (int j = 0; j < 4; j++)
            wmma::store_matrix_sync(myCs + i * 16 * GC_LD + j * 16, c[i][j], GC_LD, wmma::mem_row_major);
    __syncwarp();

#pragma unroll
    for (int f = lane; f < 512; f += 32) {
        int r = f >> 4, cc = (f & 15) * 4;
        int gr = rowBase + wm * 32 + r;
        int gc = colBase + wn * 64 + cc;
        if (gr < M) {
            float4 v = *(float4*)(myCs + r * GC_LD + cc);
            float* dst = C + (size_t)gr * Nc + gc;
            if (gc + 3 < Nc) *(float4*)dst = v;
            else {
                if (gc + 0 < Nc) dst[0] = v.x;
                if (gc + 1 < Nc) dst[1] = v.y;
                if (gc + 2 < Nc) dst[2] = v.z;
            }
        }
    }
}

// ---------------- fused gate-GEMM + GRU --------------------------------------
// Block owns 64 nodes. A tiles (aggr rows + h rows, all K=200 cols, tf32-
// rounded) live in SMEM for the whole kernel. Loop over 4 chunks of 64 gate
// columns; per chunk accumulate 6 gate tiles (i_r,i_z,i_n from aggr; h_r,h_z,
// h_n from h) with wmma, then apply the GRU in the epilogue and write h_out.
#define FBM 64
#define FCW 64
#define NCHUNK 4
#define FA_LD 216          // 208 data cols (200 + zero pad) + 8 pad
#define FB_LD 392          // 6*64 slab cols + 8 pad
#define EPI_LD 196         // 6*32 + 4 pad
#define OFF_AA 0
#define OFF_AH (FBM * FA_LD)                     // 13824
#define OFF_UN (2 * FBM * FA_LD)                 // 27648
#define UN_FLOATS (8 * 16 * EPI_LD)              // 25088 (>= 16*FB_LD = 6272)
#define OFF_BIH (OFF_UN + UN_FLOATS)             // 52736
#define OFF_BHH (OFF_BIH + 608)
#define FUSED_SMEM_FLOATS (OFF_BHH + 608)
#define FUSED_SMEM_BYTES (FUSED_SMEM_FLOATS * 4) // 215,808 B

__global__ __launch_bounds__(256) void fused_gate_gru(
    const float* __restrict__ Aaggr, const float* __restrict__ Ah,
    const float* __restrict__ Bih, const float* __restrict__ Bhh,
    const float* __restrict__ b_ih, const float* __restrict__ b_hh,
    float* __restrict__ h_out)
{
    extern __shared__ float smem[];
    const int tid  = threadIdx.x;
    const int wid  = tid >> 5;
    const int lane = tid & 31;
    const int wm   = wid & 3;      // warp row: 16 nodes
    const int wn   = wid >> 2;     // warp col: 32 of the 64 chunk cols
    const int rowBase = blockIdx.x * FBM;

    // ---- stage A tiles (aggr + h), tf32-rounded, zero-padded ----
    for (int f = tid; f < 2 * 64 * 54; f += 256) {
        int mtx = f / (64 * 54);
        int rem = f - mtx * (64 * 54);
        int r = rem / 54, c4 = rem - r * 54;
        float4 v = make_float4(0.f, 0.f, 0.f, 0.f);
        int gr = rowBase + r;
        if (gr < N_NODES && c4 < 50) {
            const float* src = (mtx ? Ah : Aaggr) + (size_t)gr * D + c4 * 4;
            v = *(const float4*)src;
        }
        v.x = wmma::__float_to_tf32(v.x); v.y = wmma::__float_to_tf32(v.y);
        v.z = wmma::__float_to_tf32(v.z); v.w = wmma::__float_to_tf32(v.w);
        *(float4*)(smem + (mtx ? OFF_AH : OFF_AA) + r * FA_LD + c4 * 4) = v;
    }
    // ---- stage biases (full precision) ----
    for (int i = tid; i < D3; i += 256) {
        smem[OFF_BIH + i] = b_ih[i];
        smem[OFF_BHH + i] = b_hh[i];
    }
    __syncthreads();

    for (int chunk = 0; chunk < NCHUNK; chunk++) {
        const int c0 = chunk * FCW;

        wmma::fragment<wmma::accumulator, 16, 16, 8, float> acc[6][2];
#pragma unroll
        for (int g = 0; g < 6; g++)
#pragma unroll
            for (int j = 0; j < 2; j++) wmma::fill_fragment(acc[g][j], 0.f);

        // prefetch B slab for k0=0 into registers (6 float4 per thread)
        float4 pf[6];
#pragma unroll
        for (int i = 0; i < 6; i++) {
            int idx = tid + i * 256;         // 0..1535
            int r = idx / 96, c4 = idx - r * 96;
            int col = c4 * 4;                // 0..380
            int s = col >> 6, c = col & 63;  // slab, within-slab col
            float4 v = make_float4(0.f, 0.f, 0.f, 0.f);
            if (r < D && c0 + c < D) {
                const float* src = (s < 3 ? Bih : Bhh)
                                 + (size_t)r * D3 + (s % 3) * D + c0 + c;
                v = *(const float4*)src;
            }
            pf[i] = v;
        }

        for (int it = 0; it < 13; it++) {
            __syncthreads();   // Bs/epi region free (prev compute or epi done)
#pragma unroll
            for (int i = 0; i < 6; i++) {
                int idx = tid + i * 256;
                int r = idx / 96, c4 = idx - r * 96;
                float4 v = pf[i];
                v.x = wmma::__float_to_tf32(v.x); v.y = wmma::__float_to_tf32(v.y);
                v.z = wmma::__float_to_tf32(v.z); v.w = wmma::__float_to_tf32(v.w);
                *(float4*)(smem + OFF_UN + r * FB_LD + c4 * 4) = v;
            }
            __syncthreads();

            if (it < 12) {
                const int k0n = (it + 1) * 16;
#pragma unroll
                for (int i = 0; i < 6; i++) {
                    int idx = tid + i * 256;
                    int r = idx / 96, c4 = idx - r * 96;
                    int col = c4 * 4;
                    int s = col >> 6, c = col & 63;
                    float4 v = make_float4(0.f, 0.f, 0.f, 0.f);
                    if (k0n + r < D && c0 + c < D) {
                        const float* src = (s < 3 ? Bih : Bhh)
                                         + (size_t)(k0n + r) * D3 + (s % 3) * D + c0 + c;
                        v = *(const float4*)src;
                    }
                    pf[i] = v;
                }
            }

            const int k0 = it * 16;
#pragma unroll
            for (int ks = 0; ks < 2; ks++) {
                const int kpos = k0 + ks * 8;
                wmma::fragment<wmma::matrix_a, 16, 16, 8, wmma::precision::tf32, wmma::row_major> aA, aH;
                wmma::load_matrix_sync(aA, smem + OFF_AA + (wm * 16) * FA_LD + kpos, FA_LD);
                wmma::load_matrix_sync(aH, smem + OFF_AH + (wm * 16) * FA_LD + kpos, FA_LD);
#pragma unroll
                for (int g = 0; g < 6; g++) {
#pragma unroll
                    for (int j = 0; j < 2; j++) {
                        wmma::fragment<wmma::matrix_b, 16, 16, 8, wmma::precision::tf32, wmma::row_major> b;
                        wmma::load_matrix_sync(b, smem + OFF_UN + (ks * 8) * FB_LD
                                                  + g * 64 + wn * 32 + j * 16, FB_LD);
                        wmma::mma_sync(acc[g][j], (g < 3 ? aA : aH), b, acc[g][j]);
                    }
                }
            }
        }

        // ---- epilogue: GRU on this 64x64 chunk ----
        __syncthreads();       // all warps done reading Bs before epi overwrite
        float* epi = smem + OFF_UN + wid * (16 * EPI_LD);
#pragma unroll
        for (int g = 0; g < 6; g++)
#pragma unroll
            for (int j = 0; j < 2; j++)
                wmma::store_matrix_sync(epi + g * 32 + j * 16, acc[g][j], EPI_LD,
                                        wmma::mem_row_major);
        __syncwarp();

        const int gcol = c0 + wn * 32 + lane;
#pragma unroll
        for (int r = 0; r < 16; r++) {
            int grow = rowBase + wm * 16 + r;
            if (grow < N_NODES && gcol < D) {
                const float* ep = epi + r * EPI_LD;
                float ir = ep[lane]       + smem[OFF_BIH + gcol];
                float iz = ep[32 + lane]  + smem[OFF_BIH + D + gcol];
                float in = ep[64 + lane]  + smem[OFF_BIH + 2 * D + gcol];
                float hr = ep[96 + lane]  + smem[OFF_BHH + gcol];
                float hz = ep[128 + lane] + smem[OFF_BHH + D + gcol];
                float hn = ep[160 + lane] + smem[OFF_BHH + 2 * D + gcol];
                float h0 = Ah[(size_t)grow * D + gcol];   // full-precision h
                float rg = 1.f / (1.f + expf(-(ir + hr)));
                float zg = 1.f / (1.f + expf(-(iz + hz)));
                float ng = tanhf(in + rg * hn);
                h_out[(size_t)grow * D + gcol] = (1.f - zg) * ng + zg * h0;
            }
        }
        // next chunk's first __syncthreads protects epi region
    }
}

// ---------------- edge scatter-add: aggr[dst] += m[src] ----------------------
__global__ void scatter_add_kernel() {
    int idx = blockIdx.x * blockDim.x + threadIdx.x;
    if (idx >= E_EDGES * 50) return;
    int e = idx / 50;
    int c = (idx - e * 50) * 4;
    int s = g_src[e];
    int d = g_dst[e];
    float4 v = *(const float4*)(g_m + (size_t)s * D + c);
    float* out = g_aggr + (size_t)d * D + c;
    atomicAdd(out + 0, v.x);
    atomicAdd(out + 1, v.y);
    atomicAdd(out + 2, v.z);
    atomicAdd(out + 3, v.w);
}

// ---------------- relu + max-pool --------------------------------------------
__global__ void maxpool_kernel(const float* __restrict__ h) {
    int d = threadIdx.x;
    if (d >= D) return;
    float v = 0.f;  // ReLU floor
    for (int n = blockIdx.x; n < N_NODES; n += gridDim.x)
        v = fmaxf(v, h[(size_t)n * D + d]);
    atomicMax((int*)&g_pool[d], __float_as_int(v));
}

// ---------------- classifier + softmax ---------------------------------------
__global__ void logits_kernel(const float* __restrict__ cls_w,
                              const float* __restrict__ cls_b,
                              float* __restrict__ out) {
    __shared__ float s0[256], s1[256];
    int t = threadIdx.x;
    float p0 = 0.f, p1 = 0.f;
    for (int d = t; d < D; d += 256) {
        float pv = g_pool[d];
        p0 += pv * cls_w[d];
        p1 += pv * cls_w[D + d];
    }
    s0[t] = p0; s1[t] = p1;
    __syncthreads();
    for (int s = 128; s > 0; s >>= 1) {
        if (t < s) { s0[t] += s0[t + s]; s1[t] += s1[t + s]; }
        __syncthreads();
    }
    if (t == 0) {
        float l0 = s0[0] + cls_b[0], l1 = s1[0] + cls_b[1];
        float mx = fmaxf(l0, l1);
        float e0 = expf(l0 - mx), e1 = expf(l1 - mx);
        float inv = 1.f / (e0 + e1);
        out[0] = e0 * inv;
        out[1] = e1 * inv;
    }
}

// ---------------- host driver -------------------------------------------------
extern "C" void kernel_launch(void* const* d_in, const int* in_sizes, int n_in,
                              void* d_out, int out_size) {
    const float* x = 0; const float* W = 0;
    const float* w_ih = 0; const float* w_hh = 0;
    const float* b_ih = 0; const float* b_hh = 0;
    const float* cls_w = 0; const float* cls_b = 0;
    const void* ei = 0;
    for (int i = 0; i < n_in; i++) {
        int sz = in_sizes[i];
        const void* p = d_in[i];
        if      (sz == N_NODES * IN_DIM) x = (const float*)p;
        else if (sz == NUM_STEPS * D * D) W = (const float*)p;
        else if (sz == D3 * D) { if (!w_ih) w_ih = (const float*)p; else w_hh = (const float*)p; }
        else if (sz == D3)     { if (!b_ih) b_ih = (const float*)p; else b_hh = (const float*)p; }
        else if (sz == 2 * D)  cls_w = (const float*)p;
        else if (sz == 2)      cls_b = (const float*)p;
        else if (sz == 2 * E_EDGES) ei = p;
    }
    float* out = (float*)d_out;

    float *h, *h2, *m, *aggr, *Bih, *Bhh, *pool;
    cudaGetSymbolAddress((void**)&h, g_h);
    cudaGetSymbolAddress((void**)&h2, g_h2);
    cudaGetSymbolAddress((void**)&m, g_m);
    cudaGetSymbolAddress((void**)&aggr, g_aggr);
    cudaGetSymbolAddress((void**)&Bih, g_Bih);
    cudaGetSymbolAddress((void**)&Bhh, g_Bhh);
    cudaGetSymbolAddress((void**)&pool, g_pool);

    const int TB = 256;

    cudaFuncSetAttribute(gemm_tf32, cudaFuncAttributeMaxDynamicSharedMemorySize,
                         GEMM_SMEM_BYTES);
    cudaFuncSetAttribute(fused_gate_gru, cudaFuncAttributeMaxDynamicSharedMemorySize,
                         FUSED_SMEM_BYTES);

    detect_ei_kernel<<<1, 32>>>((const unsigned int*)ei);
    convert_ei_kernel<<<(E_EDGES + TB - 1) / TB, TB>>>(ei);

    init_h_kernel<<<(N_NODES * D + TB - 1) / TB, TB>>>(x);
    transpose_kernel<<<(D3 * D + TB - 1) / TB, TB>>>(w_ih, Bih);
    transpose_kernel<<<(D3 * D + TB - 1) / TB, TB>>>(w_hh, Bhh);

    dim3 gridM((D + BNG - 1) / BNG, (N_NODES + BMG - 1) / BMG);   // 2 x 782
    const int gridF = (N_NODES + FBM - 1) / FBM;                   // 1563

    float* hc = h;
    float* hn = h2;
    for (int step = 0; step < NUM_STEPS; step++) {
        // m = h @ W[step]
        gemm_tf32<<<gridM, TB, GEMM_SMEM_BYTES>>>(hc, W + (size_t)step * D * D, m,
                                                  N_NODES, D, D);
        // aggr = scatter_add(m[src] -> dst)
        zero4_kernel<<<(N_NODES * 50 + TB - 1) / TB, TB>>>(aggr, N_NODES * 50);
        scatter_add_kernel<<<(E_EDGES * 50 + TB - 1) / TB, TB>>>();
        // h_next = GRU(aggr @ w_ih^T, h @ w_hh^T, h)  [fused]
        fused_gate_gru<<<gridF, TB, FUSED_SMEM_BYTES>>>(aggr, hc, Bih, Bhh,
                                                        b_ih, b_hh, hn);
        float* t = hc; hc = hn; hn = t;
    }

    zero4_kernel<<<1, TB>>>(pool, D / 4);
    maxpool_kernel<<<1024, TB>>>(hc);
    logits_kernel<<<1, TB>>>(cls_w, cls_b, out);
}

// round 13
// speedup vs baseline: 1.6534x; 1.6534x over previous
#include <cuda_runtime.h>
#include <math.h>
#include <mma.h>

using namespace nvcuda;

#define N_NODES 100000
#define E_EDGES 400000
#define IN_DIM  100
#define D       200
#define D3      600
#define NUM_STEPS 4

// ---------------- scratch (static device globals; 16B-aligned) ---------------
__device__ __align__(16) float g_h   [(size_t)N_NODES * D];
__device__ __align__(16) float g_m   [(size_t)N_NODES * D];
__device__ __align__(16) float g_aggr[(size_t)N_NODES * D];
__device__ __align__(16) float g_gi  [(size_t)N_NODES * D3];
__device__ __align__(16) float g_gh  [(size_t)N_NODES * D3];
__device__ __align__(16) float g_Bih [D * D3];
__device__ __align__(16) float g_Bhh [D * D3];
__device__ __align__(16) float g_pool[D];
__device__ int g_src[E_EDGES];
__device__ int g_dst[E_EDGES];
__device__ int g_ei_is64;

// ---------------- edge-index dtype detection + conversion --------------------
__global__ void detect_ei_kernel(const unsigned int* __restrict__ w) {
    if (threadIdx.x == 0) {
        int is64 = 1;
        for (int i = 0; i < 4096; i++)
            if (w[2 * i + 1] != 0u) { is64 = 0; break; }
        g_ei_is64 = is64;
    }
}

__global__ void convert_ei_kernel(const void* __restrict__ ei) {
    int e = blockIdx.x * blockDim.x + threadIdx.x;
    if (e >= E_EDGES) return;
    int s, d;
    if (g_ei_is64) {
        const long long* p = (const long long*)ei;
        s = (int)p[e];
        d = (int)p[E_EDGES + e];
    } else {
        const int* p = (const int*)ei;
        s = p[e];
        d = p[E_EDGES + e];
    }
    s = min(max(s, 0), N_NODES - 1);
    d = min(max(d, 0), N_NODES - 1);
    g_src[e] = s;
    g_dst[e] = d;
}

// ---------------- helpers ----------------------------------------------------
__global__ void zero4_kernel(float* __restrict__ p, int n4) {
    int i = blockIdx.x * blockDim.x + threadIdx.x;
    if (i < n4) ((float4*)p)[i] = make_float4(0.f, 0.f, 0.f, 0.f);
}

__global__ void init_h_kernel(const float* __restrict__ x) {
    int idx = blockIdx.x * blockDim.x + threadIdx.x;
    if (idx >= N_NODES * D) return;
    int n = idx / D, d = idx - n * D;
    g_h[idx] = (d < IN_DIM) ? x[n * IN_DIM + d] : 0.f;
}

// w: [D3, D] row-major  ->  o: [D, D3] row-major  (o = w^T)
__global__ void transpose_kernel(const float* __restrict__ w, float* __restrict__ o) {
    int idx = blockIdx.x * blockDim.x + threadIdx.x;
    if (idx >= D3 * D) return;
    int r = idx / D, c = idx - r * D;
    o[c * D3 + r] = w[idx];
}

// ---------------- TF32 tensor-core GEMM: C[M,Nc] = A[M,K] @ B[K,Nc] ----------
// Block 128x128, BK=16, 256 threads, 8 warps in 4(M)x2(N), warp tile 32x64.
// Double-buffered SMEM (ping-pong) + register prefetch; tf32 CVT at staging;
// interior warps store accumulators straight to global; edge warps use a
// staged fallback overlaying the (idle) A/B buffers.
// Requires: K % 4 == 0, Nc % 4 == 0 (true here: K=200, Nc∈{200,600}).
#define BMG 128
#define BNG 128
#define BKG 16
#define GA_LD 20                       // 16 + 4 pad
#define GB_LD 132                      // 128 + 4 pad
#define GC_LD 68                       // 64 + 4 pad (fallback scratch)
#define STAGE_FLOATS (BMG * GA_LD + BKG * GB_LD)   // 2560 + 2112 = 4672
#define GEMM_SMEM_BYTES (2 * STAGE_FLOATS * 4)     // 37376 B

__device__ __forceinline__ float4 tf32x4(float4 v) {
    v.x = wmma::__float_to_tf32(v.x); v.y = wmma::__float_to_tf32(v.y);
    v.z = wmma::__float_to_tf32(v.z); v.w = wmma::__float_to_tf32(v.w);
    return v;
}

__global__ __launch_bounds__(256, 2) void gemm_tf32(
    const float* __restrict__ A, const float* __restrict__ B, float* __restrict__ C,
    int M, int Nc, int K)
{
    extern __shared__ float smem[];
    const int tid  = threadIdx.x;
    const int wid  = tid >> 5;
    const int lane = tid & 31;
    const int wm   = wid & 3;
    const int wn   = wid >> 2;
    const int rowBase = blockIdx.y * BMG;
    const int colBase = blockIdx.x * BNG;
    const int NIT = (K + BKG - 1) / BKG;

    // staging coordinates: A tile = 128 rows x 4 float4 (idx = r*4 + c4),
    // B tile = 16 rows x 32 float4 (idx = r*32 + c4). 2 float4/thread each.
    const int aR0 = tid >> 2,          aC0 = (tid & 3) * 4;           // idx = tid
    const int aR1 = (tid + 256) >> 2,  aC1 = ((tid + 256) & 3) * 4;   // idx = tid+256
    const int bR0 = tid >> 5,          bC0 = (tid & 31) * 4;
    const int bR1 = (tid + 256) >> 5,  bC1 = ((tid + 256) & 31) * 4;

    wmma::fragment<wmma::accumulator, 16, 16, 8, float> c[2][4];
#pragma unroll
    for (int i = 0; i < 2; i++)
#pragma unroll
        for (int j = 0; j < 4; j++) wmma::fill_fragment(c[i][j], 0.f);

    float4 pa0, pa1, pb0, pb1;

    // guarded float4 load helpers (K%4==0, Nc%4==0 => in-bounds implies full vec)
    auto ldA = [&](int k0, int r, int cc) -> float4 {
        int gr = rowBase + r, gc = k0 + cc;
        if (gr < M && gc < K) return *(const float4*)(A + (size_t)gr * K + gc);
        return make_float4(0.f, 0.f, 0.f, 0.f);
    };
    auto ldB = [&](int k0, int r, int cc) -> float4 {
        int gr = k0 + r, gc = colBase + cc;
        if (gr < K && gc < Nc) return *(const float4*)(B + (size_t)gr * Nc + gc);
        return make_float4(0.f, 0.f, 0.f, 0.f);
    };
    auto stStage = [&](int buf) {
        float* As = smem + buf * STAGE_FLOATS;
        float* Bs = As + BMG * GA_LD;
        *(float4*)(As + aR0 * GA_LD + aC0) = tf32x4(pa0);
        *(float4*)(As + aR1 * GA_LD + aC1) = tf32x4(pa1);
        *(float4*)(Bs + bR0 * GB_LD + bC0) = tf32x4(pb0);
        *(float4*)(Bs + bR1 * GB_LD + bC1) = tf32x4(pb1);
    };
    auto ldTile = [&](int it) {
        int k0 = it * BKG;
        pa0 = ldA(k0, aR0, aC0); pa1 = ldA(k0, aR1, aC1);
        pb0 = ldB(k0, bR0, bC0); pb1 = ldB(k0, bR1, bC1);
    };

    // prologue: tile 0 -> buf0; prefetch tile 1
    ldTile(0);
    stStage(0);
    if (NIT > 1) ldTile(1);
    __syncthreads();

    for (int it = 0; it < NIT; it++) {
        const int cur = it & 1;
        if (it + 1 < NIT) {
            stStage(1 - cur);                 // tile it+1 (regs) -> other buffer
            if (it + 2 < NIT) ldTile(it + 2); // prefetch tile it+2
        }
        const float* As = smem + cur * STAGE_FLOATS;
        const float* Bs = As + BMG * GA_LD;
#pragma unroll
        for (int ks = 0; ks < 2; ks++) {
            const int kk = ks * 8;
            wmma::fragment<wmma::matrix_a, 16, 16, 8, wmma::precision::tf32, wmma::row_major> a0, a1;
            wmma::load_matrix_sync(a0, As + (wm * 32 + 0)  * GA_LD + kk, GA_LD);
            wmma::load_matrix_sync(a1, As + (wm * 32 + 16) * GA_LD + kk, GA_LD);
#pragma unroll
            for (int j = 0; j < 4; j++) {
                wmma::fragment<wmma::matrix_b, 16, 16, 8, wmma::precision::tf32, wmma::row_major> b;
                wmma::load_matrix_sync(b, Bs + kk * GB_LD + wn * 64 + j * 16, GB_LD);
                wmma::mma_sync(c[0][j], a0, b, c[0][j]);
                wmma::mma_sync(c[1][j], a1, b, c[1][j]);
            }
        }
        __syncthreads();
    }

    // ---- epilogue ----
    const bool fast = (rowBase + wm * 32 + 32 <= M) && (colBase + wn * 64 + 64 <= Nc);
    if (fast) {
#pragma unroll
        for (int i = 0; i < 2; i++)
#pragma unroll
            for (int j = 0; j < 4; j++)
                wmma::store_matrix_sync(
                    C + (size_t)(rowBase + wm * 32 + i * 16) * Nc
                      + colBase + wn * 64 + j * 16,
                    c[i][j], Nc, wmma::mem_row_major);
    }
    // slow path: two waves (wn==0, then wn==1) through SMEM scratch
#pragma unroll
    for (int wave = 0; wave < 2; wave++) {
        __syncthreads();   // wave 0: also guarantees compute reads of SMEM done
        if (!fast && wn == wave) {
            float* sc = smem + wm * (32 * GC_LD);
#pragma unroll
            for (int i = 0; i < 2; i++)
#pragma unroll
                for (int j = 0; j < 4; j++)
                    wmma::store_matrix_sync(sc + i * 16 * GC_LD + j * 16, c[i][j],
                                            GC_LD, wmma::mem_row_major);
            __syncwarp();
#pragma unroll
            for (int f = lane; f < 512; f += 32) {     // 32 rows x 16 float4
                int r = f >> 4, cc = (f & 15) * 4;
                int gr = rowBase + wm * 32 + r;
                int gc = colBase + wn * 64 + cc;
                if (gr < M && gc < Nc)
                    *(float4*)(C + (size_t)gr * Nc + gc) = *(float4*)(sc + r * GC_LD + cc);
            }
        }
    }
}

// ---------------- edge scatter-add: aggr[dst] += m[src] ----------------------
__global__ void scatter_add_kernel() {
    int idx = blockIdx.x * blockDim.x + threadIdx.x;
    if (idx >= E_EDGES * 50) return;
    int e = idx / 50;
    int c = (idx - e * 50) * 4;
    int s = g_src[e];
    int d = g_dst[e];
    float4 v = *(const float4*)(g_m + (size_t)s * D + c);
    float* out = g_aggr + (size_t)d * D + c;
    atomicAdd(out + 0, v.x);
    atomicAdd(out + 1, v.y);
    atomicAdd(out + 2, v.z);
    atomicAdd(out + 3, v.w);
}

// ---------------- GRU elementwise --------------------------------------------
__device__ __forceinline__ float gru1(float ir, float iz, float inn,
                                      float hr, float hz, float hn, float h) {
    float r = 1.f / (1.f + expf(-(ir + hr)));
    float z = 1.f / (1.f + expf(-(iz + hz)));
    float n = tanhf(inn + r * hn);
    return (1.f - z) * n + z * h;
}

__global__ void gru_kernel(const float* __restrict__ b_ih, const float* __restrict__ b_hh) {
    int idx = blockIdx.x * blockDim.x + threadIdx.x;
    if (idx >= N_NODES * 50) return;
    int n = idx / 50;
    int c = (idx - n * 50) * 4;
    size_t gbase = (size_t)n * D3;
    float4 ir  = *(const float4*)(g_gi + gbase + c);
    float4 iz  = *(const float4*)(g_gi + gbase + D + c);
    float4 inn = *(const float4*)(g_gi + gbase + 2 * D + c);
    float4 hr  = *(const float4*)(g_gh + gbase + c);
    float4 hz  = *(const float4*)(g_gh + gbase + D + c);
    float4 hn  = *(const float4*)(g_gh + gbase + 2 * D + c);
    float bir0 = b_ih[c],         bir1 = b_ih[c + 1],         bir2 = b_ih[c + 2],         bir3 = b_ih[c + 3];
    float biz0 = b_ih[D + c],     biz1 = b_ih[D + c + 1],     biz2 = b_ih[D + c + 2],     biz3 = b_ih[D + c + 3];
    float bin0 = b_ih[2 * D + c], bin1 = b_ih[2 * D + c + 1], bin2 = b_ih[2 * D + c + 2], bin3 = b_ih[2 * D + c + 3];
    float bhr0 = b_hh[c],         bhr1 = b_hh[c + 1],         bhr2 = b_hh[c + 2],         bhr3 = b_hh[c + 3];
    float bhz0 = b_hh[D + c],     bhz1 = b_hh[D + c + 1],     bhz2 = b_hh[D + c + 2],     bhz3 = b_hh[D + c + 3];
    float bhn0 = b_hh[2 * D + c], bhn1 = b_hh[2 * D + c + 1], bhn2 = b_hh[2 * D + c + 2], bhn3 = b_hh[2 * D + c + 3];
    float4 h = *(float4*)(g_h + (size_t)n * D + c);
    h.x = gru1(ir.x + bir0, iz.x + biz0, inn.x + bin0, hr.x + bhr0, hz.x + bhz0, hn.x + bhn0, h.x);
    h.y = gru1(ir.y + bir1, iz.y + biz1, inn.y + bin1, hr.y + bhr1, hz.y + bhz1, hn.y + bhn1, h.y);
    h.z = gru1(ir.z + bir2, iz.z + biz2, inn.z + bin2, hr.z + bhr2, hz.z + bhz2, hn.z + bhn2, h.z);
    h.w = gru1(ir.w + bir3, iz.w + biz3, inn.w + bin3, hr.w + bhr3, hz.w + bhz3, hn.w + bhn3, h.w);
    *(float4*)(g_h + (size_t)n * D + c) = h;
}

// ---------------- relu + max-pool --------------------------------------------
__global__ void maxpool_kernel() {
    int d = threadIdx.x;
    if (d >= D) return;
    float v = 0.f;  // ReLU floor
    for (int n = blockIdx.x; n < N_NODES; n += gridDim.x)
        v = fmaxf(v, g_h[(size_t)n * D + d]);
    atomicMax((int*)&g_pool[d], __float_as_int(v));
}

// ---------------- classifier + softmax ---------------------------------------
__global__ void logits_kernel(const float* __restrict__ cls_w,
                              const float* __restrict__ cls_b,
                              float* __restrict__ out) {
    __shared__ float s0[256], s1[256];
    int t = threadIdx.x;
    float p0 = 0.f, p1 = 0.f;
    for (int d = t; d < D; d += 256) {
        float pv = g_pool[d];
        p0 += pv * cls_w[d];
        p1 += pv * cls_w[D + d];
    }
    s0[t] = p0; s1[t] = p1;
    __syncthreads();
    for (int s = 128; s > 0; s >>= 1) {
        if (t < s) { s0[t] += s0[t + s]; s1[t] += s1[t + s]; }
        __syncthreads();
    }
    if (t == 0) {
        float l0 = s0[0] + cls_b[0], l1 = s1[0] + cls_b[1];
        float mx = fmaxf(l0, l1);
        float e0 = expf(l0 - mx), e1 = expf(l1 - mx);
        float inv = 1.f / (e0 + e1);
        out[0] = e0 * inv;
        out[1] = e1 * inv;
    }
}

// ---------------- host driver -------------------------------------------------
extern "C" void kernel_launch(void* const* d_in, const int* in_sizes, int n_in,
                              void* d_out, int out_size) {
    const float* x = 0; const float* W = 0;
    const float* w_ih = 0; const float* w_hh = 0;
    const float* b_ih = 0; const float* b_hh = 0;
    const float* cls_w = 0; const float* cls_b = 0;
    const void* ei = 0;
    for (int i = 0; i < n_in; i++) {
        int sz = in_sizes[i];
        const void* p = d_in[i];
        if      (sz == N_NODES * IN_DIM) x = (const float*)p;
        else if (sz == NUM_STEPS * D * D) W = (const float*)p;
        else if (sz == D3 * D) { if (!w_ih) w_ih = (const float*)p; else w_hh = (const float*)p; }
        else if (sz == D3)     { if (!b_ih) b_ih = (const float*)p; else b_hh = (const float*)p; }
        else if (sz == 2 * D)  cls_w = (const float*)p;
        else if (sz == 2)      cls_b = (const float*)p;
        else if (sz == 2 * E_EDGES) ei = p;
    }
    float* out = (float*)d_out;

    float *h, *m, *aggr, *gi, *gh, *Bih, *Bhh, *pool;
    cudaGetSymbolAddress((void**)&h, g_h);
    cudaGetSymbolAddress((void**)&m, g_m);
    cudaGetSymbolAddress((void**)&aggr, g_aggr);
    cudaGetSymbolAddress((void**)&gi, g_gi);
    cudaGetSymbolAddress((void**)&gh, g_gh);
    cudaGetSymbolAddress((void**)&Bih, g_Bih);
    cudaGetSymbolAddress((void**)&Bhh, g_Bhh);
    cudaGetSymbolAddress((void**)&pool, g_pool);

    const int TB = 256;

    cudaFuncSetAttribute(gemm_tf32, cudaFuncAttributeMaxDynamicSharedMemorySize,
                         GEMM_SMEM_BYTES);

    detect_ei_kernel<<<1, 32>>>((const unsigned int*)ei);
    convert_ei_kernel<<<(E_EDGES + TB - 1) / TB, TB>>>(ei);

    init_h_kernel<<<(N_NODES * D + TB - 1) / TB, TB>>>(x);
    transpose_kernel<<<(D3 * D + TB - 1) / TB, TB>>>(w_ih, Bih);
    transpose_kernel<<<(D3 * D + TB - 1) / TB, TB>>>(w_hh, Bhh);

    dim3 gridM((D  + BNG - 1) / BNG, (N_NODES + BMG - 1) / BMG);   // 2 x 782
    dim3 gridG((D3 + BNG - 1) / BNG, (N_NODES + BMG - 1) / BMG);   // 5 x 782

    for (int step = 0; step < NUM_STEPS; step++) {
        // m = h @ W[step]
        gemm_tf32<<<gridM, TB, GEMM_SMEM_BYTES>>>(h, W + (size_t)step * D * D, m,
                                                  N_NODES, D, D);
        // aggr = scatter_add(m[src] -> dst)
        zero4_kernel<<<(N_NODES * 50 + TB - 1) / TB, TB>>>(aggr, N_NODES * 50);
        scatter_add_kernel<<<(E_EDGES * 50 + TB - 1) / TB, TB>>>();
        // gi = aggr @ w_ih^T ; gh = h @ w_hh^T
        gemm_tf32<<<gridG, TB, GEMM_SMEM_BYTES>>>(aggr, Bih, gi, N_NODES, D3, D);
        gemm_tf32<<<gridG, TB, GEMM_SMEM_BYTES>>>(h, Bhh, gh, N_NODES, D3, D);
        // h = GRU(aggr-gates, h-gates, h)
        gru_kernel<<<(N_NODES * 50 + TB - 1) / TB, TB>>>(b_ih, b_hh);
    }

    zero4_kernel<<<1, TB>>>(pool, D / 4);
    maxpool_kernel<<<1024, TB>>>();
    logits_kernel<<<1, TB>>>(cls_w, cls_b, out);
}

// round 15
// speedup vs baseline: 1.8009x; 1.0893x over previous
#include <cuda_runtime.h>
#include <math.h>
#include <mma.h>

using namespace nvcuda;

#define N_NODES 100000
#define E_EDGES 400000
#define IN_DIM  100
#define D       200
#define D3      600
#define NUM_STEPS 4

// ---------------- scratch (static device globals; 16B-aligned) ---------------
__device__ __align__(16) float g_h   [(size_t)N_NODES * D];
__device__ __align__(16) float g_m   [(size_t)N_NODES * D];
__device__ __align__(16) float g_aggr[(size_t)N_NODES * D];
__device__ __align__(16) float g_gi  [(size_t)N_NODES * D3];
__device__ __align__(16) float g_gh  [(size_t)N_NODES * D3];
__device__ __align__(16) float g_Bih [D * D3];
__device__ __align__(16) float g_Bhh [D * D3];
__device__ __align__(16) float g_pool[D];
__device__ int g_src[E_EDGES];
__device__ int g_dst[E_EDGES];
__device__ int g_ei_is64;
// CSR (dst-indexed) scratch
__device__ int g_cnt[N_NODES];
__device__ int g_row_ptr[N_NODES + 1];
__device__ int g_cursor[N_NODES];
__device__ int g_col[E_EDGES];

// ---------------- edge-index dtype detection + conversion --------------------
__global__ void detect_ei_kernel(const unsigned int* __restrict__ w) {
    if (threadIdx.x == 0) {
        int is64 = 1;
        for (int i = 0; i < 4096; i++)
            if (w[2 * i + 1] != 0u) { is64 = 0; break; }
        g_ei_is64 = is64;
    }
}

__global__ void convert_ei_kernel(const void* __restrict__ ei) {
    int e = blockIdx.x * blockDim.x + threadIdx.x;
    if (e >= E_EDGES) return;
    int s, d;
    if (g_ei_is64) {
        const long long* p = (const long long*)ei;
        s = (int)p[e];
        d = (int)p[E_EDGES + e];
    } else {
        const int* p = (const int*)ei;
        s = p[e];
        d = p[E_EDGES + e];
    }
    s = min(max(s, 0), N_NODES - 1);
    d = min(max(d, 0), N_NODES - 1);
    g_src[e] = s;
    g_dst[e] = d;
}

// ---------------- CSR build ---------------------------------------------------
__global__ void zero_counts_kernel() {
    int i = blockIdx.x * blockDim.x + threadIdx.x;
    if (i < N_NODES) g_cnt[i] = 0;
}

__global__ void count_kernel() {
    int e = blockIdx.x * blockDim.x + threadIdx.x;
    if (e < E_EDGES) atomicAdd(&g_cnt[g_dst[e]], 1);
}

// single block, 1024 threads: hierarchical exclusive scan of g_cnt -> row_ptr
__global__ __launch_bounds__(1024) void prefix_kernel() {
    __shared__ int ssum[1024];
    const int t = threadIdx.x;
    const int CHUNK = (N_NODES + 1023) / 1024;   // 98
    int begin = t * CHUNK;
    int end = min(begin + CHUNK, N_NODES);
    int s = 0;
    for (int i = begin; i < end; i++) s += g_cnt[i];
    ssum[t] = s;
    __syncthreads();
    for (int off = 1; off < 1024; off <<= 1) {
        int v = (t >= off) ? ssum[t - off] : 0;
        __syncthreads();
        ssum[t] += v;
        __syncthreads();
    }
    int base = (t == 0) ? 0 : ssum[t - 1];
    for (int i = begin; i < end; i++) {
        int c = g_cnt[i];
        g_row_ptr[i] = base;
        g_cursor[i]  = base;
        base += c;
    }
    if (t == 1023) g_row_ptr[N_NODES] = ssum[1023];
}

__global__ void fill_kernel() {
    int e = blockIdx.x * blockDim.x + threadIdx.x;
    if (e >= E_EDGES) return;
    int d = g_dst[e];
    int pos = atomicAdd(&g_cursor[d], 1);
    g_col[pos] = g_src[e];
}

// ---------------- CSR gather: aggr[n] = sum_{e: dst=n} m[src[e]] -------------
// one warp per node; lane covers float4 chunks {lane, lane+32} of the 50-chunk row
__global__ void gather_aggr_kernel() {
    int gw = (blockIdx.x * blockDim.x + threadIdx.x) >> 5;
    int lane = threadIdx.x & 31;
    if (gw >= N_NODES) return;
    int start = g_row_ptr[gw], end = g_row_ptr[gw + 1];
    float4 a0 = make_float4(0.f, 0.f, 0.f, 0.f);
    float4 a1 = make_float4(0.f, 0.f, 0.f, 0.f);
    for (int e = start; e < end; e++) {
        const float4* row = (const float4*)(g_m + (size_t)g_col[e] * D);
        float4 v0 = row[lane];
        a0.x += v0.x; a0.y += v0.y; a0.z += v0.z; a0.w += v0.w;
        if (lane < 18) {
            float4 v1 = row[lane + 32];
            a1.x += v1.x; a1.y += v1.y; a1.z += v1.z; a1.w += v1.w;
        }
    }
    float4* orow = (float4*)(g_aggr + (size_t)gw * D);
    orow[lane] = a0;
    if (lane < 18) orow[lane + 32] = a1;
}

// ---------------- helpers ----------------------------------------------------
__global__ void zero4_kernel(float* __restrict__ p, int n4) {
    int i = blockIdx.x * blockDim.x + threadIdx.x;
    if (i < n4) ((float4*)p)[i] = make_float4(0.f, 0.f, 0.f, 0.f);
}

__global__ void init_h_kernel(const float* __restrict__ x) {
    int idx = blockIdx.x * blockDim.x + threadIdx.x;
    if (idx >= N_NODES * D) return;
    int n = idx / D, d = idx - n * D;
    g_h[idx] = (d < IN_DIM) ? x[n * IN_DIM + d] : 0.f;
}

// w: [D3, D] row-major  ->  o: [D, D3] row-major  (o = w^T)
__global__ void transpose_kernel(const float* __restrict__ w, float* __restrict__ o) {
    int idx = blockIdx.x * blockDim.x + threadIdx.x;
    if (idx >= D3 * D) return;
    int r = idx / D, c = idx - r * D;
    o[c * D3 + r] = w[idx];
}

// ---------------- TF32 tensor-core GEMM: C[M,Nc] = A[M,K] @ B[K,Nc] ----------
#define BMG 128
#define BNG 128
#define BKG 16
#define GA_LD 20
#define GB_LD 132
#define GC_LD 68
#define STAGE_FLOATS (BMG * GA_LD + BKG * GB_LD)   // 4672
#define GEMM_SMEM_BYTES (2 * STAGE_FLOATS * 4)     // 37376 B

__device__ __forceinline__ float4 tf32x4(float4 v) {
    v.x = wmma::__float_to_tf32(v.x); v.y = wmma::__float_to_tf32(v.y);
    v.z = wmma::__float_to_tf32(v.z); v.w = wmma::__float_to_tf32(v.w);
    return v;
}

__global__ __launch_bounds__(256, 2) void gemm_tf32(
    const float* __restrict__ A, const float* __restrict__ B, float* __restrict__ C,
    int M, int Nc, int K)
{
    extern __shared__ float smem[];
    const int tid  = threadIdx.x;
    const int wid  = tid >> 5;
    const int lane = tid & 31;
    const int wm   = wid & 3;
    const int wn   = wid >> 2;
    const int rowBase = blockIdx.y * BMG;
    const int colBase = blockIdx.x * BNG;
    const int NIT = (K + BKG - 1) / BKG;

    const int aR0 = tid >> 2,          aC0 = (tid & 3) * 4;
    const int aR1 = (tid + 256) >> 2,  aC1 = ((tid + 256) & 3) * 4;
    const int bR0 = tid >> 5,          bC0 = (tid & 31) * 4;
    const int bR1 = (tid + 256) >> 5,  bC1 = ((tid + 256) & 31) * 4;

    wmma::fragment<wmma::accumulator, 16, 16, 8, float> c[2][4];
#pragma unroll
    for (int i = 0; i < 2; i++)
#pragma unroll
        for (int j = 0; j < 4; j++) wmma::fill_fragment(c[i][j], 0.f);

    float4 pa0, pa1, pb0, pb1;

    auto ldA = [&](int k0, int r, int cc) -> float4 {
        int gr = rowBase + r, gc = k0 + cc;
        if (gr < M && gc < K) return *(const float4*)(A + (size_t)gr * K + gc);
        return make_float4(0.f, 0.f, 0.f, 0.f);
    };
    auto ldB = [&](int k0, int r, int cc) -> float4 {
        int gr = k0 + r, gc = colBase + cc;
        if (gr < K && gc < Nc) return *(const float4*)(B + (size_t)gr * Nc + gc);
        return make_float4(0.f, 0.f, 0.f, 0.f);
    };
    auto stStage = [&](int buf) {
        float* As = smem + buf * STAGE_FLOATS;
        float* Bs = As + BMG * GA_LD;
        *(float4*)(As + aR0 * GA_LD + aC0) = tf32x4(pa0);
        *(float4*)(As + aR1 * GA_LD + aC1) = tf32x4(pa1);
        *(float4*)(Bs + bR0 * GB_LD + bC0) = tf32x4(pb0);
        *(float4*)(Bs + bR1 * GB_LD + bC1) = tf32x4(pb1);
    };
    auto ldTile = [&](int it) {
        int k0 = it * BKG;
        pa0 = ldA(k0, aR0, aC0); pa1 = ldA(k0, aR1, aC1);
        pb0 = ldB(k0, bR0, bC0); pb1 = ldB(k0, bR1, bC1);
    };

    ldTile(0);
    stStage(0);
    if (NIT > 1) ldTile(1);
    __syncthreads();

    for (int it = 0; it < NIT; it++) {
        const int cur = it & 1;
        if (it + 1 < NIT) {
            stStage(1 - cur);
            if (it + 2 < NIT) ldTile(it + 2);
        }
        const float* As = smem + cur * STAGE_FLOATS;
        const float* Bs = As + BMG * GA_LD;
#pragma unroll
        for (int ks = 0; ks < 2; ks++) {
            const int kk = ks * 8;
            wmma::fragment<wmma::matrix_a, 16, 16, 8, wmma::precision::tf32, wmma::row_major> a0, a1;
            wmma::load_matrix_sync(a0, As + (wm * 32 + 0)  * GA_LD + kk, GA_LD);
            wmma::load_matrix_sync(a1, As + (wm * 32 + 16) * GA_LD + kk, GA_LD);
#pragma unroll
            for (int j = 0; j < 4; j++) {
                wmma::fragment<wmma::matrix_b, 16, 16, 8, wmma::precision::tf32, wmma::row_major> b;
                wmma::load_matrix_sync(b, Bs + kk * GB_LD + wn * 64 + j * 16, GB_LD);
                wmma::mma_sync(c[0][j], a0, b, c[0][j]);
                wmma::mma_sync(c[1][j], a1, b, c[1][j]);
            }
        }
        __syncthreads();
    }

    const bool fast = (rowBase + wm * 32 + 32 <= M) && (colBase + wn * 64 + 64 <= Nc);
    if (fast) {
#pragma unroll
        for (int i = 0; i < 2; i++)
#pragma unroll
            for (int j = 0; j < 4; j++)
                wmma::store_matrix_sync(
                    C + (size_t)(rowBase + wm * 32 + i * 16) * Nc
                      + colBase + wn * 64 + j * 16,
                    c[i][j], Nc, wmma::mem_row_major);
    }
#pragma unroll
    for (int wave = 0; wave < 2; wave++) {
        __syncthreads();
        if (!fast && wn == wave) {
            float* sc = smem + wm * (32 * GC_LD);
#pragma unroll
            for (int i = 0; i < 2; i++)
#pragma unroll
                for (int j = 0; j < 4; j++)
                    wmma::store_matrix_sync(sc + i * 16 * GC_LD + j * 16, c[i][j],
                                            GC_LD, wmma::mem_row_major);
            __syncwarp();
#pragma unroll
            for (int f = lane; f < 512; f += 32) {
                int r = f >> 4, cc = (f & 15) * 4;
                int gr = rowBase + wm * 32 + r;
                int gc = colBase + wn * 64 + cc;
                if (gr < M && gc < Nc)
                    *(float4*)(C + (size_t)gr * Nc + gc) = *(float4*)(sc + r * GC_LD + cc);
            }
        }
    }
}

// ---------------- GRU elementwise --------------------------------------------
__device__ __forceinline__ float gru1(float ir, float iz, float inn,
                                      float hr, float hz, float hn, float h) {
    float r = 1.f / (1.f + expf(-(ir + hr)));
    float z = 1.f / (1.f + expf(-(iz + hz)));
    float n = tanhf(inn + r * hn);
    return (1.f - z) * n + z * h;
}

__global__ void gru_kernel(const float* __restrict__ b_ih, const float* __restrict__ b_hh) {
    int idx = blockIdx.x * blockDim.x + threadIdx.x;
    if (idx >= N_NODES * 50) return;
    int n = idx / 50;
    int c = (idx - n * 50) * 4;
    size_t gbase = (size_t)n * D3;
    float4 ir  = *(const float4*)(g_gi + gbase + c);
    float4 iz  = *(const float4*)(g_gi + gbase + D + c);
    float4 inn = *(const float4*)(g_gi + gbase + 2 * D + c);
    float4 hr  = *(const float4*)(g_gh + gbase + c);
    float4 hz  = *(const float4*)(g_gh + gbase + D + c);
    float4 hn  = *(const float4*)(g_gh + gbase + 2 * D + c);
    float bir0 = b_ih[c],         bir1 = b_ih[c + 1],         bir2 = b_ih[c + 2],         bir3 = b_ih[c + 3];
    float biz0 = b_ih[D + c],     biz1 = b_ih[D + c + 1],     biz2 = b_ih[D + c + 2],     biz3 = b_ih[D + c + 3];
    float bin0 = b_ih[2 * D + c], bin1 = b_ih[2 * D + c + 1], bin2 = b_ih[2 * D + c + 2], bin3 = b_ih[2 * D + c + 3];
    float bhr0 = b_hh[c],         bhr1 = b_hh[c + 1],         bhr2 = b_hh[c + 2],         bhr3 = b_hh[c + 3];
    float bhz0 = b_hh[D + c],     bhz1 = b_hh[D + c + 1],     bhz2 = b_hh[D + c + 2],     bhz3 = b_hh[D + c + 3];
    float bhn0 = b_hh[2 * D + c], bhn1 = b_hh[2 * D + c + 1], bhn2 = b_hh[2 * D + c + 2], bhn3 = b_hh[2 * D + c + 3];
    float4 h = *(float4*)(g_h + (size_t)n * D + c);
    h.x = gru1(ir.x + bir0, iz.x + biz0, inn.x + bin0, hr.x + bhr0, hz.x + bhz0, hn.x + bhn0, h.x);
    h.y = gru1(ir.y + bir1, iz.y + biz1, inn.y + bin1, hr.y + bhr1, hz.y + bhz1, hn.y + bhn1, h.y);
    h.z = gru1(ir.z + bir2, iz.z + biz2, inn.z + bin2, hr.z + bhr2, hz.z + bhz2, hn.z + bhn2, h.z);
    h.w = gru1(ir.w + bir3, iz.w + biz3, inn.w + bin3, hr.w + bhr3, hz.w + bhz3, hn.w + bhn3, h.w);
    *(float4*)(g_h + (size_t)n * D + c) = h;
}

// ---------------- relu + max-pool --------------------------------------------
__global__ void maxpool_kernel() {
    int d = threadIdx.x;
    if (d >= D) return;
    float v = 0.f;  // ReLU floor
    for (int n = blockIdx.x; n < N_NODES; n += gridDim.x)
        v = fmaxf(v, g_h[(size_t)n * D + d]);
    atomicMax((int*)&g_pool[d], __float_as_int(v));
}

// ---------------- classifier + softmax ---------------------------------------
__global__ void logits_kernel(const float* __restrict__ cls_w,
                              const float* __restrict__ cls_b,
                              float* __restrict__ out) {
    __shared__ float s0[256], s1[256];
    int t = threadIdx.x;
    float p0 = 0.f, p1 = 0.f;
    for (int d = t; d < D; d += 256) {
        float pv = g_pool[d];
        p0 += pv * cls_w[d];
        p1 += pv * cls_w[D + d];
    }
    s0[t] = p0; s1[t] = p1;
    __syncthreads();
    for (int s = 128; s > 0; s >>= 1) {
        if (t < s) { s0[t] += s0[t + s]; s1[t] += s1[t + s]; }
        __syncthreads();
    }
    if (t == 0) {
        float l0 = s0[0] + cls_b[0], l1 = s1[0] + cls_b[1];
        float mx = fmaxf(l0, l1);
        float e0 = expf(l0 - mx), e1 = expf(l1 - mx);
        float inv = 1.f / (e0 + e1);
        out[0] = e0 * inv;
        out[1] = e1 * inv;
    }
}

// ---------------- host driver -------------------------------------------------
extern "C" void kernel_launch(void* const* d_in, const int* in_sizes, int n_in,
                              void* d_out, int out_size) {
    const float* x = 0; const float* W = 0;
    const float* w_ih = 0; const float* w_hh = 0;
    const float* b_ih = 0; const float* b_hh = 0;
    const float* cls_w = 0; const float* cls_b = 0;
    const void* ei = 0;
    for (int i = 0; i < n_in; i++) {
        int sz = in_sizes[i];
        const void* p = d_in[i];
        if      (sz == N_NODES * IN_DIM) x = (const float*)p;
        else if (sz == NUM_STEPS * D * D) W = (const float*)p;
        else if (sz == D3 * D) { if (!w_ih) w_ih = (const float*)p; else w_hh = (const float*)p; }
        else if (sz == D3)     { if (!b_ih) b_ih = (const float*)p; else b_hh = (const float*)p; }
        else if (sz == 2 * D)  cls_w = (const float*)p;
        else if (sz == 2)      cls_b = (const float*)p;
        else if (sz == 2 * E_EDGES) ei = p;
    }
    float* out = (float*)d_out;

    float *h, *m, *aggr, *gi, *gh, *Bih, *Bhh, *pool;
    cudaGetSymbolAddress((void**)&h, g_h);
    cudaGetSymbolAddress((void**)&m, g_m);
    cudaGetSymbolAddress((void**)&aggr, g_aggr);
    cudaGetSymbolAddress((void**)&gi, g_gi);
    cudaGetSymbolAddress((void**)&gh, g_gh);
    cudaGetSymbolAddress((void**)&Bih, g_Bih);
    cudaGetSymbolAddress((void**)&Bhh, g_Bhh);
    cudaGetSymbolAddress((void**)&pool, g_pool);

    const int TB = 256;

    cudaFuncSetAttribute(gemm_tf32, cudaFuncAttributeMaxDynamicSharedMemorySize,
                         GEMM_SMEM_BYTES);

    dim3 gridM((D  + BNG - 1) / BNG, (N_NODES + BMG - 1) / BMG);   // 2 x 782
    dim3 gridG((D3 + BNG - 1) / BNG, (N_NODES + BMG - 1) / BMG);   // 5 x 782

    // Launch order chosen so launch index 5 (ncu -s 5 -c 1) is the first
    // gemm_tf32, not a trivial kernel.
    init_h_kernel<<<(N_NODES * D + TB - 1) / TB, TB>>>(x);           // 0
    transpose_kernel<<<(D3 * D + TB - 1) / TB, TB>>>(w_ih, Bih);     // 1
    transpose_kernel<<<(D3 * D + TB - 1) / TB, TB>>>(w_hh, Bhh);     // 2
    detect_ei_kernel<<<1, 32>>>((const unsigned int*)ei);            // 3
    convert_ei_kernel<<<(E_EDGES + TB - 1) / TB, TB>>>(ei);          // 4

    for (int step = 0; step < NUM_STEPS; step++) {
        // m = h @ W[step]     (step 0: launch index 5 -> ncu capture)
        gemm_tf32<<<gridM, TB, GEMM_SMEM_BYTES>>>(h, W + (size_t)step * D * D, m,
                                                  N_NODES, D, D);
        if (step == 0) {
            // build CSR (dst -> sorted src list) once
            zero_counts_kernel<<<(N_NODES + TB - 1) / TB, TB>>>();
            count_kernel<<<(E_EDGES + TB - 1) / TB, TB>>>();
            prefix_kernel<<<1, 1024>>>();
            fill_kernel<<<(E_EDGES + TB - 1) / TB, TB>>>();
        }
        // aggr[n] = sum over in-edges (no atomics, no zero pass)
        gather_aggr_kernel<<<(N_NODES * 32 + TB - 1) / TB, TB>>>();
        // gi = aggr @ w_ih^T ; gh = h @ w_hh^T
        gemm_tf32<<<gridG, TB, GEMM_SMEM_BYTES>>>(aggr, Bih, gi, N_NODES, D3, D);
        gemm_tf32<<<gridG, TB, GEMM_SMEM_BYTES>>>(h, Bhh, gh, N_NODES, D3, D);
        // h = GRU(aggr-gates, h-gates, h)
        gru_kernel<<<(N_NODES * 50 + TB - 1) / TB, TB>>>(b_ih, b_hh);
    }

    zero4_kernel<<<1, TB>>>(pool, D / 4);
    maxpool_kernel<<<1024, TB>>>();
    logits_kernel<<<1, TB>>>(cls_w, cls_b, out);
}